// round 11
// baseline (speedup 1.0000x reference)
#include <cuda_runtime.h>
#include <cuda_fp16.h>
#include <cstdint>

#define NTOT 16384
#define KN   16
#define NP   15
#define CIN  64
#define COUT 128
#define KTOT (NP * CIN)        // 960

// ---------------- global scratch (allowed: __device__ arrays) ----------------
__device__ __half g_A[(size_t)NTOT * KTOT];     // [n][k] k-major, fp16
__device__ __half g_B[COUT * KTOT];             // [cout][k] k-major (= W^T), fp16
__device__ int    g_cnt;                        // monotone W-conversion counter

typedef unsigned long long u64;
typedef unsigned int u32;

__device__ __forceinline__ u32 h2pk(float a, float b) {
    __half ha = __float2half_rn(a), hb = __float2half_rn(b);
    unsigned short ua = *reinterpret_cast<unsigned short*>(&ha);
    unsigned short ub = *reinterpret_cast<unsigned short*>(&hb);
    return (u32)ua | ((u32)ub << 16);
}
__device__ __forceinline__ u32 smem_u32(const void* p) {
    u32 a; asm("{ .reg .u64 t; cvta.to.shared.u64 t, %1; cvt.u32.u64 %0, t; }"
               : "=r"(a) : "l"(p));
    return a;
}
__device__ __forceinline__ void ldmx4(u32* r, u32 addr) {
    asm volatile("ldmatrix.sync.aligned.m8n8.x4.shared.b16 {%0,%1,%2,%3}, [%4];"
                 : "=r"(r[0]), "=r"(r[1]), "=r"(r[2]), "=r"(r[3]) : "r"(addr));
}
__device__ __forceinline__ void ldmx4t(u32* r, u32 addr) {
    asm volatile("ldmatrix.sync.aligned.m8n8.x4.trans.shared.b16 {%0,%1,%2,%3}, [%4];"
                 : "=r"(r[0]), "=r"(r[1]), "=r"(r[2]), "=r"(r[3]) : "r"(addr));
}
__device__ __forceinline__ void mma_f16(float* d, const u32* a, const u32* b) {
    asm volatile("mma.sync.aligned.m16n8k16.row.col.f32.f16.f16.f32 "
                 "{%0,%1,%2,%3}, {%4,%5,%6,%7}, {%8,%9}, {%0,%1,%2,%3};"
                 : "+f"(d[0]), "+f"(d[1]), "+f"(d[2]), "+f"(d[3])
                 : "r"(a[0]), "r"(a[1]), "r"(a[2]), "r"(a[3]),
                   "r"(b[0]), "r"(b[1]));
}

// =============== fused kernel: grid 256, 256 threads, M-tile 64 ===============
// smem (union): phase A: f 64KB | infl 16KB | kp/q/nidx ; phase B: 2x24KB
#define NT 256
#define QB 64            // queries per CTA
#define OFF_F    0
#define OFF_INFL 65536
#define OFF_KP   81920
#define OFF_Q    82112
#define OFF_NIDX 82944
#define SMEM_TOT 87040

#define NCHUNK 15
#define ATILE  8192      // 64 x 128B
#define BTILE  16384     // 128 x 128B
#define BUFB   (ATILE + BTILE)

__global__ __launch_bounds__(NT, 2)
void kpconv_fused(const float* __restrict__ query,
                  const float* __restrict__ support,
                  const int*   __restrict__ nidx,
                  const float* __restrict__ feats,
                  const float* __restrict__ kp,
                  const float* __restrict__ W,
                  float* __restrict__ out)
{
    extern __shared__ char sm[];
    const u32 sb = smem_u32(sm);
    __half* s_infl = (__half*)(sm + OFF_INFL);
    float*  s_kp   = (float*)(sm + OFF_KP);
    float*  s_q    = (float*)(sm + OFF_Q);
    int*    s_nidx = (int*)(sm + OFF_NIDX);

    const int tid = threadIdx.x;
    const int bid = blockIdx.x;
    const int m0  = bid * QB;

    // ---- step 0: W conversion by CTAs 0..119 (first thing; tiny) ----
    if (bid < 120) {
        int idx4 = bid * NT + tid;            // 0..30719, 4 k-elems each
        int n  = idx4 / 240;
        int kq = idx4 - n * 240;
        int k  = kq * 4;
        int p  = k >> 6, cin = k & 63;
        const float* wp = W + p * CIN * COUT + cin * COUT + n;
        float w0 = __ldg(wp);
        float w1 = __ldg(wp + COUT);
        float w2 = __ldg(wp + 2 * COUT);
        float w3 = __ldg(wp + 3 * COUT);
        uint2 vh = make_uint2(h2pk(w0, w1), h2pk(w2, w3));
        *(uint2*)(g_B + (size_t)n * KTOT + k) = vh;
        __threadfence();
        __syncthreads();
        if (tid == 0) atomicAdd(&g_cnt, 1);
    }

    // ---- phase A: per-CTA aggregation of its own 64 queries ----
    for (int i = tid; i < QB * KN; i += NT) s_nidx[i] = nidx[m0 * KN + i];
    if (tid < NP * 3)  s_kp[tid] = kp[tid];
    if (tid < QB * 3)  s_q[tid]  = query[m0 * 3 + tid];
    __syncthreads();

    const int wid  = tid >> 5;
    const int lane = tid & 31;

    // frag addressing constants (verified in R9)
    const int aprow = (lane & 7) + ((lane >> 3) & 1) * 8;
    const u32 abh   = (u32)(((lane >> 4) & 1) * 16);
    const int mgrp  = lane >> 3;
    const int krow  = (mgrp & 1) * 8 + (lane & 7);
    const u32 cbyte0 = (u32)((mgrp >> 1) * 16);

    #pragma unroll
    for (int sbch = 0; sbch < 2; sbch++) {
        __syncthreads();   // previous sub-batch fully consumed

        // gather features -> fp16 swizzled smem tile (32 queries)
        #pragma unroll
        for (int i = 0; i < 32; i++) {
            int g   = tid + i * NT;           // 0..8191
            int row = g >> 4;                 // local (q,k) row 0..511
            int q16 = g & 15;
            int m   = s_nidx[sbch * 512 + row];
            uint4 v = __ldg((const uint4*)(feats + (size_t)m * CIN) + q16);
            u32 lo = h2pk(__uint_as_float(v.x), __uint_as_float(v.y));
            u32 hi = h2pk(__uint_as_float(v.z), __uint_as_float(v.w));
            u32 off = (u32)(row * 128) +
                      ((u32)((q16 >> 1) * 16) ^ ((u32)(row & 7) * 16)) +
                      (u32)((q16 & 1) * 8);
            *(uint2*)(sm + OFF_F + off) = make_uint2(lo, hi);
        }

        // influences -> fp16 smem [q][p(16) x k(16)]
        #pragma unroll
        for (int pp = 0; pp < 2; pp++) {
            int pair = tid + pp * NT;         // 0..511
            int qq = pair >> 4;
            int kk = pair & 15;
            int m  = s_nidx[sbch * 512 + pair];
            int qg = sbch * 32 + qq;
            float rx = support[m * 3 + 0] - s_q[qg * 3 + 0];
            float ry = support[m * 3 + 1] - s_q[qg * 3 + 1];
            float rz = support[m * 3 + 2] - s_q[qg * 3 + 2];
            __half* ib = s_infl + qq * 256 + kk;
            #pragma unroll
            for (int p = 0; p < NP; p++) {
                float dx = rx - s_kp[p * 3 + 0];
                float dy = ry - s_kp[p * 3 + 1];
                float dz = rz - s_kp[p * 3 + 2];
                float d  = sqrtf(fmaf(dx, dx, fmaf(dy, dy, dz * dz)));
                ib[p * 16] = __float2half_rn(fmaxf(1.0f - d, 0.0f));
            }
            ib[15 * 16] = __half(0.0f);
        }
        __syncthreads();

        // per-query mma aggregation: D[16p x 64c] = infl[16,16] @ f[16,64]
        #pragma unroll
        for (int i = 0; i < 4; i++) {
            const int q = wid * 4 + i;        // local query 0..31

            u32 a[4];
            ldmx4(a, sb + OFF_INFL + (u32)(q * 512 + aprow * 32) + abh);

            float acc[8][4];
            #pragma unroll
            for (int g = 0; g < 8; g++)
                #pragma unroll
                for (int e = 0; e < 4; e++) acc[g][e] = 0.0f;

            const int frow = q * 16 + krow;
            const u32 fbase = sb + OFF_F + (u32)(frow * 128);
            const u32 swz   = (u32)((krow & 7) * 16);
            #pragma unroll
            for (int cc = 0; cc < 4; cc++) {
                u32 b[4];
                ldmx4t(b, fbase + (((u32)(cc * 32) + cbyte0) ^ swz));
                mma_f16(acc[2 * cc],     a, &b[0]);
                mma_f16(acc[2 * cc + 1], a, &b[2]);
            }

            // stage D -> fp16 into dead f-tile rows of query q (swizzled)
            const int prow = lane >> 2;
            const int c4   = lane & 3;
            #pragma unroll
            for (int g = 0; g < 8; g++) {
                u32 lo = h2pk(acc[g][0], acc[g][1]);
                u32 hi = h2pk(acc[g][2], acc[g][3]);
                u32 x = (u32)(g * 16);
                *(u32*)(sm + OFF_F + (q * 16 + prow) * 128 +
                        ((x ^ ((u32)(prow & 7) * 16)) + (u32)(c4 * 4))) = lo;
                *(u32*)(sm + OFF_F + (q * 16 + prow + 8) * 128 +
                        ((x ^ ((u32)((prow + 8) & 7) * 16)) + (u32)(c4 * 4))) = hi;
            }
            __syncwarp();

            // coalesced write-out: 15 p-rows x 128B -> g_A row (m0 + sbch*32 + q)
            #pragma unroll
            for (int rnd = 0; rnd < 4; rnd++) {
                int u = lane + rnd * 32;
                if (u < 120) {
                    int p = u >> 3, j = u & 7;
                    uint4 v = *(uint4*)(sm + OFF_F + (q * 16 + p) * 128 +
                                        (((u32)(j * 16)) ^ ((u32)(p & 7) * 16)));
                    *(uint4*)(g_A + (size_t)(m0 + sbch * 32 + q) * KTOT
                              + p * CIN + j * 8) = v;
                }
            }
            __syncwarp();
        }
    }

    // ---- barrier: own A rows visible at L2; B conversion done grid-wide ----
    __threadfence();
    if (tid == 0) { while (atomicAdd(&g_cnt, 0) < 120) { } }
    __syncthreads();

    // ---- phase B: GEMM out[64 x 128] = A_own[64 x 960] @ B^T ----
    const int wm = wid >> 2;        // 0..1 (M groups of 32)
    const int wn = wid & 3;         // 0..3 (N groups of 32)

    const int a_row  = wm * 32 + (lane & 7) + ((lane >> 3) & 1) * 8;
    const int a_bh   = ((lane >> 4) & 1) * 16;
    const u32 a_mask = (u32)((a_row & 7) * 16);
    const int b_row  = wn * 32 + (lane & 7) + ((lane >> 4) & 1) * 8;
    const int b_bh   = ((lane >> 3) & 1) * 16;
    const u32 b_mask = (u32)((b_row & 7) * 16);

    float acc[2][4][4];
    #pragma unroll
    for (int mi = 0; mi < 2; mi++)
        #pragma unroll
        for (int ni = 0; ni < 4; ni++)
            #pragma unroll
            for (int e = 0; e < 4; e++) acc[mi][ni][e] = 0.0f;

    auto load_chunk = [&](int c) {
        u32 dstb = sb + (u32)(c & 1) * BUFB;
        #pragma unroll
        for (int j = 0; j < 6; j++) {
            int idx = tid + j * NT;               // 0..1535
            const __half* src;
            u32 dst;
            if (idx < 512) {                      // A tile: 64 rows
                int row = idx >> 3, c16 = idx & 7;
                src = g_A + (size_t)(m0 + row) * KTOT + c * 64 + c16 * 8;
                dst = dstb + (u32)(row * 128 + ((c16 * 16) ^ ((row & 7) * 16)));
            } else {                              // B tile: 128 rows
                int w = idx - 512;
                int row = w >> 3, c16 = w & 7;
                src = g_B + (size_t)row * KTOT + c * 64 + c16 * 8;
                dst = dstb + ATILE
                    + (u32)(row * 128 + ((c16 * 16) ^ ((row & 7) * 16)));
            }
            asm volatile("cp.async.cg.shared.global [%0], [%1], 16;"
                         :: "r"(dst), "l"(src) : "memory");
        }
        asm volatile("cp.async.commit_group;" ::: "memory");
    };

    load_chunk(0);

    for (int c = 0; c < NCHUNK; c++) {
        if (c + 1 < NCHUNK) {
            load_chunk(c + 1);
            asm volatile("cp.async.wait_group 1;" ::: "memory");
        } else {
            asm volatile("cp.async.wait_group 0;" ::: "memory");
        }
        __syncthreads();

        const u32 bufb  = sb + (u32)(c & 1) * BUFB;
        const u32 aBase = bufb + (u32)(a_row * 128);
        const u32 bBase = bufb + ATILE + (u32)(b_row * 128);

        #pragma unroll
        for (int ks = 0; ks < 4; ks++) {
            const u32 aOff = (u32)((ks * 32 + a_bh)) ^ a_mask;
            const u32 bOff = (u32)((ks * 32 + b_bh)) ^ b_mask;

            u32 b[8];
            #pragma unroll
            for (int nj = 0; nj < 2; nj++)
                ldmx4(&b[nj * 4], bBase + (u32)(nj * 16 * 128) + bOff);

            #pragma unroll
            for (int mi = 0; mi < 2; mi++) {
                u32 a[4];
                ldmx4(a, aBase + (u32)(mi * 16 * 128) + aOff);
                #pragma unroll
                for (int ni = 0; ni < 4; ni++)
                    mma_f16(acc[mi][ni], a, &b[(ni >> 1) * 4 + (ni & 1) * 2]);
            }
        }
        __syncthreads();
    }

    // ---- epilogue ----
    #pragma unroll
    for (int mi = 0; mi < 2; mi++) {
        int row = m0 + wm * 32 + mi * 16 + (lane >> 2);
        #pragma unroll
        for (int ni = 0; ni < 4; ni++) {
            int col = wn * 32 + ni * 8 + (lane & 3) * 2;
            *(float2*)(out + (size_t)row * COUT + col) =
                make_float2(acc[mi][ni][0], acc[mi][ni][1]);
            *(float2*)(out + (size_t)(row + 8) * COUT + col) =
                make_float2(acc[mi][ni][2], acc[mi][ni][3]);
        }
    }
}

// ================= launch =================
extern "C" void kernel_launch(void* const* d_in, const int* in_sizes, int n_in,
                              void* d_out, int out_size) {
    const float* query   = (const float*)d_in[0];
    const float* support = (const float*)d_in[1];
    const int*   nidx    = (const int*)d_in[2];
    const float* feats   = (const float*)d_in[3];
    const float* W       = (const float*)d_in[4];
    const float* kp      = (const float*)d_in[5];
    float* out = (float*)d_out;

    cudaFuncSetAttribute(kpconv_fused,
                         cudaFuncAttributeMaxDynamicSharedMemorySize, SMEM_TOT);
    kpconv_fused<<<NTOT / QB, NT, SMEM_TOT>>>(
        query, support, nidx, feats, kp, W, out);
}

// round 12
// speedup vs baseline: 1.1328x; 1.1328x over previous
#include <cuda_runtime.h>
#include <cuda_fp16.h>
#include <cstdint>

#define NTOT 16384
#define KN   16
#define NP   15
#define CIN  64
#define COUT 128
#define KTOT (NP * CIN)        // 960

// ---------------- global scratch (allowed: __device__ arrays) ----------------
__device__ __half g_A[(size_t)NTOT * KTOT];     // [n][k] k-major, fp16
__device__ __half g_B[COUT * KTOT];             // [cout][k] k-major (= W^T), fp16
__device__ __half g_F[(size_t)NTOT * CIN];      // features pre-converted to fp16
__device__ int    g_cnt;                        // monotone conversion counter

typedef unsigned long long u64;
typedef unsigned int u32;

__device__ __forceinline__ u32 h2pk(float a, float b) {
    __half ha = __float2half_rn(a), hb = __float2half_rn(b);
    unsigned short ua = *reinterpret_cast<unsigned short*>(&ha);
    unsigned short ub = *reinterpret_cast<unsigned short*>(&hb);
    return (u32)ua | ((u32)ub << 16);
}
__device__ __forceinline__ u32 smem_u32(const void* p) {
    u32 a; asm("{ .reg .u64 t; cvta.to.shared.u64 t, %1; cvt.u32.u64 %0, t; }"
               : "=r"(a) : "l"(p));
    return a;
}
__device__ __forceinline__ void ldmx4(u32* r, u32 addr) {
    asm volatile("ldmatrix.sync.aligned.m8n8.x4.shared.b16 {%0,%1,%2,%3}, [%4];"
                 : "=r"(r[0]), "=r"(r[1]), "=r"(r[2]), "=r"(r[3]) : "r"(addr));
}
__device__ __forceinline__ void ldmx4t(u32* r, u32 addr) {
    asm volatile("ldmatrix.sync.aligned.m8n8.x4.trans.shared.b16 {%0,%1,%2,%3}, [%4];"
                 : "=r"(r[0]), "=r"(r[1]), "=r"(r[2]), "=r"(r[3]) : "r"(addr));
}
__device__ __forceinline__ void mma_f16(float* d, const u32* a, const u32* b) {
    asm volatile("mma.sync.aligned.m16n8k16.row.col.f32.f16.f16.f32 "
                 "{%0,%1,%2,%3}, {%4,%5,%6,%7}, {%8,%9}, {%0,%1,%2,%3};"
                 : "+f"(d[0]), "+f"(d[1]), "+f"(d[2]), "+f"(d[3])
                 : "r"(a[0]), "r"(a[1]), "r"(a[2]), "r"(a[3]),
                   "r"(b[0]), "r"(b[1]));
}

// =============== fused kernel: grid 256, 256 threads, M-tile 64 ===============
#define NT 256
#define QB 64            // queries per CTA
#define OFF_F    0
#define OFF_INFL 65536
#define OFF_KP   81920
#define OFF_Q    82112
#define OFF_NIDX 82944
#define SMEM_TOT 87040

#define NCHUNK 15
#define ATILE  8192      // 64 x 128B
#define BTILE  16384     // 128 x 128B
#define BUFB   (ATILE + BTILE)

__global__ __launch_bounds__(NT, 2)
void kpconv_fused(const float* __restrict__ query,
                  const float* __restrict__ support,
                  const int*   __restrict__ nidx,
                  const float* __restrict__ feats,
                  const float* __restrict__ kp,
                  const float* __restrict__ W,
                  float* __restrict__ out)
{
    extern __shared__ char sm[];
    const u32 sb = smem_u32(sm);
    __half* s_infl = (__half*)(sm + OFF_INFL);
    float*  s_kp   = (float*)(sm + OFF_KP);
    float*  s_q    = (float*)(sm + OFF_Q);
    int*    s_nidx = (int*)(sm + OFF_NIDX);

    const int tid = threadIdx.x;
    const int bid = blockIdx.x;
    const int m0  = bid * QB;

    // ---- step 0a: W conversion by CTAs 0..119 ----
    if (bid < 120) {
        int idx4 = bid * NT + tid;            // 0..30719, 4 k-elems each
        int n  = idx4 / 240;
        int kq = idx4 - n * 240;
        int k  = kq * 4;
        int p  = k >> 6, cin = k & 63;
        const float* wp = W + p * CIN * COUT + cin * COUT + n;
        float w0 = __ldg(wp);
        float w1 = __ldg(wp + COUT);
        float w2 = __ldg(wp + 2 * COUT);
        float w3 = __ldg(wp + 3 * COUT);
        uint2 vh = make_uint2(h2pk(w0, w1), h2pk(w2, w3));
        *(uint2*)(g_B + (size_t)n * KTOT + k) = vh;
    }

    // ---- step 0b: feats->fp16 conversion, each CTA its own 64-row slice ----
    {
        const float* fsrc = feats + (size_t)bid * 64 * CIN;
        __half*      fdst = g_F   + (size_t)bid * 64 * CIN;
        #pragma unroll
        for (int t = 0; t < 4; t++) {
            int idx = tid + t * NT;           // 0..1023 uint4 groups
            uint4 v = __ldg((const uint4*)fsrc + idx);
            uint2 h = make_uint2(h2pk(__uint_as_float(v.x), __uint_as_float(v.y)),
                                 h2pk(__uint_as_float(v.z), __uint_as_float(v.w)));
            *(uint2*)(fdst + idx * 4) = h;
        }
    }
    __threadfence();
    __syncthreads();
    if (tid == 0) atomicAdd(&g_cnt, 1);

    // ---- load per-CTA metadata ----
    for (int i = tid; i < QB * KN; i += NT) s_nidx[i] = nidx[m0 * KN + i];
    if (tid < NP * 3)  s_kp[tid] = kp[tid];
    if (tid < QB * 3)  s_q[tid]  = query[m0 * 3 + tid];

    // ---- grid-wide wait: g_F (and g_B) complete ----
    if (tid == 0) { while (atomicAdd(&g_cnt, 0) < 256) { } }
    __syncthreads();
    __threadfence();

    const int wid  = tid >> 5;
    const int lane = tid & 31;

    // frag addressing constants (verified)
    const int aprow = (lane & 7) + ((lane >> 3) & 1) * 8;
    const u32 abh   = (u32)(((lane >> 4) & 1) * 16);
    const int mgrp  = lane >> 3;
    const int krow  = (mgrp & 1) * 8 + (lane & 7);
    const u32 cbyte0 = (u32)((mgrp >> 1) * 16);

    #pragma unroll
    for (int sbch = 0; sbch < 2; sbch++) {
        __syncthreads();   // previous sub-batch fully consumed

        // gather fp16 features -> swizzled smem tile (32 queries, 512 rows)
        #pragma unroll
        for (int i = 0; i < 16; i++) {
            int g   = tid + i * NT;           // 0..4095
            int row = g >> 3;                 // local (q,k) row 0..511
            int c16 = g & 7;
            int m   = s_nidx[sbch * 512 + row];
            uint4 v = __ldg((const uint4*)(g_F + (size_t)m * CIN) + c16);
            u32 off = (u32)(row * 128) + (((u32)(c16 * 16)) ^ ((u32)(row & 7) * 16));
            *(uint4*)(sm + OFF_F + off) = v;
        }

        // influences -> fp16 smem [q][p(16) x k(16)]
        #pragma unroll
        for (int pp = 0; pp < 2; pp++) {
            int pair = tid + pp * NT;         // 0..511
            int qq = pair >> 4;
            int kk = pair & 15;
            int m  = s_nidx[sbch * 512 + pair];
            int qg = sbch * 32 + qq;
            float rx = support[m * 3 + 0] - s_q[qg * 3 + 0];
            float ry = support[m * 3 + 1] - s_q[qg * 3 + 1];
            float rz = support[m * 3 + 2] - s_q[qg * 3 + 2];
            __half* ib = s_infl + qq * 256 + kk;
            #pragma unroll
            for (int p = 0; p < NP; p++) {
                float dx = rx - s_kp[p * 3 + 0];
                float dy = ry - s_kp[p * 3 + 1];
                float dz = rz - s_kp[p * 3 + 2];
                float d  = sqrtf(fmaf(dx, dx, fmaf(dy, dy, dz * dz)));
                ib[p * 16] = __float2half_rn(fmaxf(1.0f - d, 0.0f));
            }
            ib[15 * 16] = __half(0.0f);
        }
        __syncthreads();

        // per-query mma aggregation: D[16p x 64c] = infl[16,16] @ f[16,64]
        #pragma unroll
        for (int i = 0; i < 4; i++) {
            const int q = wid * 4 + i;        // local query 0..31

            u32 a[4];
            ldmx4(a, sb + OFF_INFL + (u32)(q * 512 + aprow * 32) + abh);

            float acc[8][4];
            #pragma unroll
            for (int g = 0; g < 8; g++)
                #pragma unroll
                for (int e = 0; e < 4; e++) acc[g][e] = 0.0f;

            const int frow = q * 16 + krow;
            const u32 fbase = sb + OFF_F + (u32)(frow * 128);
            const u32 swz   = (u32)((krow & 7) * 16);
            #pragma unroll
            for (int cc = 0; cc < 4; cc++) {
                u32 b[4];
                ldmx4t(b, fbase + (((u32)(cc * 32) + cbyte0) ^ swz));
                mma_f16(acc[2 * cc],     a, &b[0]);
                mma_f16(acc[2 * cc + 1], a, &b[2]);
            }

            // stage D -> fp16 into dead f-tile rows of query q (swizzled)
            const int prow = lane >> 2;
            const int c4   = lane & 3;
            #pragma unroll
            for (int g = 0; g < 8; g++) {
                u32 lo = h2pk(acc[g][0], acc[g][1]);
                u32 hi = h2pk(acc[g][2], acc[g][3]);
                u32 x = (u32)(g * 16);
                *(u32*)(sm + OFF_F + (q * 16 + prow) * 128 +
                        ((x ^ ((u32)(prow & 7) * 16)) + (u32)(c4 * 4))) = lo;
                *(u32*)(sm + OFF_F + (q * 16 + prow + 8) * 128 +
                        ((x ^ ((u32)((prow + 8) & 7) * 16)) + (u32)(c4 * 4))) = hi;
            }
            __syncwarp();

            // coalesced write-out: 15 p-rows x 128B -> g_A row (m0 + sbch*32 + q)
            #pragma unroll
            for (int rnd = 0; rnd < 4; rnd++) {
                int u = lane + rnd * 32;
                if (u < 120) {
                    int p = u >> 3, j = u & 7;
                    uint4 v = *(uint4*)(sm + OFF_F + (q * 16 + p) * 128 +
                                        (((u32)(j * 16)) ^ ((u32)(p & 7) * 16)));
                    *(uint4*)(g_A + (size_t)(m0 + sbch * 32 + q) * KTOT
                              + p * CIN + j * 8) = v;
                }
            }
            __syncwarp();
        }
    }

    // ---- own A rows visible at L2 ----
    __threadfence();
    __syncthreads();

    // ---- phase B: GEMM out[64 x 128] = A_own[64 x 960] @ B^T ----
    const int wm = wid >> 2;        // 0..1 (M groups of 32)
    const int wn = wid & 3;         // 0..3 (N groups of 32)

    const int a_row  = wm * 32 + (lane & 7) + ((lane >> 3) & 1) * 8;
    const int a_bh   = ((lane >> 4) & 1) * 16;
    const u32 a_mask = (u32)((a_row & 7) * 16);
    const int b_row  = wn * 32 + (lane & 7) + ((lane >> 4) & 1) * 8;
    const int b_bh   = ((lane >> 3) & 1) * 16;
    const u32 b_mask = (u32)((b_row & 7) * 16);

    float acc[2][4][4];
    #pragma unroll
    for (int mi = 0; mi < 2; mi++)
        #pragma unroll
        for (int ni = 0; ni < 4; ni++)
            #pragma unroll
            for (int e = 0; e < 4; e++) acc[mi][ni][e] = 0.0f;

    auto load_chunk = [&](int c) {
        u32 dstb = sb + (u32)(c & 1) * BUFB;
        #pragma unroll
        for (int j = 0; j < 6; j++) {
            int idx = tid + j * NT;               // 0..1535
            const __half* src;
            u32 dst;
            if (idx < 512) {                      // A tile: 64 rows
                int row = idx >> 3, c16 = idx & 7;
                src = g_A + (size_t)(m0 + row) * KTOT + c * 64 + c16 * 8;
                dst = dstb + (u32)(row * 128 + ((c16 * 16) ^ ((row & 7) * 16)));
            } else {                              // B tile: 128 rows
                int w = idx - 512;
                int row = w >> 3, c16 = w & 7;
                src = g_B + (size_t)row * KTOT + c * 64 + c16 * 8;
                dst = dstb + ATILE
                    + (u32)(row * 128 + ((c16 * 16) ^ ((row & 7) * 16)));
            }
            asm volatile("cp.async.cg.shared.global [%0], [%1], 16;"
                         :: "r"(dst), "l"(src) : "memory");
        }
        asm volatile("cp.async.commit_group;" ::: "memory");
    };

    load_chunk(0);

    for (int c = 0; c < NCHUNK; c++) {
        if (c + 1 < NCHUNK) {
            load_chunk(c + 1);
            asm volatile("cp.async.wait_group 1;" ::: "memory");
        } else {
            asm volatile("cp.async.wait_group 0;" ::: "memory");
        }
        __syncthreads();

        const u32 bufb  = sb + (u32)(c & 1) * BUFB;
        const u32 aBase = bufb + (u32)(a_row * 128);
        const u32 bBase = bufb + ATILE + (u32)(b_row * 128);

        #pragma unroll
        for (int ks = 0; ks < 4; ks++) {
            const u32 aOff = (u32)((ks * 32 + a_bh)) ^ a_mask;
            const u32 bOff = (u32)((ks * 32 + b_bh)) ^ b_mask;

            u32 b[8];
            #pragma unroll
            for (int nj = 0; nj < 2; nj++)
                ldmx4(&b[nj * 4], bBase + (u32)(nj * 16 * 128) + bOff);

            #pragma unroll
            for (int mi = 0; mi < 2; mi++) {
                u32 a[4];
                ldmx4(a, aBase + (u32)(mi * 16 * 128) + aOff);
                #pragma unroll
                for (int ni = 0; ni < 4; ni++)
                    mma_f16(acc[mi][ni], a, &b[(ni >> 1) * 4 + (ni & 1) * 2]);
            }
        }
        __syncthreads();
    }

    // ---- epilogue ----
    #pragma unroll
    for (int mi = 0; mi < 2; mi++) {
        int row = m0 + wm * 32 + mi * 16 + (lane >> 2);
        #pragma unroll
        for (int ni = 0; ni < 4; ni++) {
            int col = wn * 32 + ni * 8 + (lane & 3) * 2;
            *(float2*)(out + (size_t)row * COUT + col) =
                make_float2(acc[mi][ni][0], acc[mi][ni][1]);
            *(float2*)(out + (size_t)(row + 8) * COUT + col) =
                make_float2(acc[mi][ni][2], acc[mi][ni][3]);
        }
    }
}

// ================= launch =================
extern "C" void kernel_launch(void* const* d_in, const int* in_sizes, int n_in,
                              void* d_out, int out_size) {
    const float* query   = (const float*)d_in[0];
    const float* support = (const float*)d_in[1];
    const int*   nidx    = (const int*)d_in[2];
    const float* feats   = (const float*)d_in[3];
    const float* W       = (const float*)d_in[4];
    const float* kp      = (const float*)d_in[5];
    float* out = (float*)d_out;

    cudaFuncSetAttribute(kpconv_fused,
                         cudaFuncAttributeMaxDynamicSharedMemorySize, SMEM_TOT);
    kpconv_fused<<<NTOT / QB, NT, SMEM_TOT>>>(
        query, support, nidx, feats, kp, W, out);
}

// round 13
// speedup vs baseline: 1.1398x; 1.0062x over previous
#include <cuda_runtime.h>
#include <cuda_fp16.h>
#include <cstdint>

#define NTOT 16384
#define KN   16
#define NP   15
#define CIN  64
#define COUT 128
#define KTOT (NP * CIN)        // 960

// ---------------- global scratch (allowed: __device__ arrays) ----------------
__device__ __half g_A[(size_t)NTOT * KTOT];     // [n][k] k-major, fp16
__device__ __half g_B[COUT * KTOT];             // [cout][k] k-major (= W^T), fp16
__device__ __half g_F[(size_t)NTOT * CIN];      // features pre-converted to fp16
__device__ int    g_cnt;                        // monotone conversion counter

typedef unsigned long long u64;
typedef unsigned int u32;

__device__ __forceinline__ u32 h2pk(float a, float b) {
    __half ha = __float2half_rn(a), hb = __float2half_rn(b);
    unsigned short ua = *reinterpret_cast<unsigned short*>(&ha);
    unsigned short ub = *reinterpret_cast<unsigned short*>(&hb);
    return (u32)ua | ((u32)ub << 16);
}
__device__ __forceinline__ u32 smem_u32(const void* p) {
    u32 a; asm("{ .reg .u64 t; cvta.to.shared.u64 t, %1; cvt.u32.u64 %0, t; }"
               : "=r"(a) : "l"(p));
    return a;
}
__device__ __forceinline__ void ldmx4(u32* r, u32 addr) {
    asm volatile("ldmatrix.sync.aligned.m8n8.x4.shared.b16 {%0,%1,%2,%3}, [%4];"
                 : "=r"(r[0]), "=r"(r[1]), "=r"(r[2]), "=r"(r[3]) : "r"(addr));
}
__device__ __forceinline__ void ldmx4t(u32* r, u32 addr) {
    asm volatile("ldmatrix.sync.aligned.m8n8.x4.trans.shared.b16 {%0,%1,%2,%3}, [%4];"
                 : "=r"(r[0]), "=r"(r[1]), "=r"(r[2]), "=r"(r[3]) : "r"(addr));
}
__device__ __forceinline__ void mma_f16(float* d, const u32* a, const u32* b) {
    asm volatile("mma.sync.aligned.m16n8k16.row.col.f32.f16.f16.f32 "
                 "{%0,%1,%2,%3}, {%4,%5,%6,%7}, {%8,%9}, {%0,%1,%2,%3};"
                 : "+f"(d[0]), "+f"(d[1]), "+f"(d[2]), "+f"(d[3])
                 : "r"(a[0]), "r"(a[1]), "r"(a[2]), "r"(a[3]),
                   "r"(b[0]), "r"(b[1]));
}

// ====== fused kernel: grid 512, 256 threads, QB=32, target 4 CTAs/SM ======
#define NT 256
#define QB 32
#define SB 16            // queries per sub-batch
#define OFF_F    0       // 256 rows x 128B = 32768
#define OFF_INFL 32768   // 16q x 256 halves = 8192
#define OFF_KP   40960   // 192
#define OFF_Q    41152   // 384
#define OFF_NIDX 41536   // 2048 -> end 43584
#define SMEM_TOT 44032

#define NCHUNK 15
#define ATILE  4096      // 32 x 128B
#define BTILE  16384     // 128 x 128B
#define BUFB   (ATILE + BTILE)   // 20480; two buffers fit below 40960

__global__ __launch_bounds__(NT, 4)
void kpconv_fused(const float* __restrict__ query,
                  const float* __restrict__ support,
                  const int*   __restrict__ nidx,
                  const float* __restrict__ feats,
                  const float* __restrict__ kp,
                  const float* __restrict__ W,
                  float* __restrict__ out)
{
    extern __shared__ char sm[];
    const u32 sb = smem_u32(sm);
    __half* s_infl = (__half*)(sm + OFF_INFL);
    float*  s_kp   = (float*)(sm + OFF_KP);
    float*  s_q    = (float*)(sm + OFF_Q);
    int*    s_nidx = (int*)(sm + OFF_NIDX);

    const int tid = threadIdx.x;
    const int bid = blockIdx.x;
    const int m0  = bid * QB;

    // ---- step 0a: W conversion by CTAs 0..119 ----
    if (bid < 120) {
        int idx4 = bid * NT + tid;            // 0..30719, 4 k-elems each
        int n  = idx4 / 240;
        int kq = idx4 - n * 240;
        int k  = kq * 4;
        int p  = k >> 6, cin = k & 63;
        const float* wp = W + p * CIN * COUT + cin * COUT + n;
        float w0 = __ldg(wp);
        float w1 = __ldg(wp + COUT);
        float w2 = __ldg(wp + 2 * COUT);
        float w3 = __ldg(wp + 3 * COUT);
        uint2 vh = make_uint2(h2pk(w0, w1), h2pk(w2, w3));
        *(uint2*)(g_B + (size_t)n * KTOT + k) = vh;
    }

    // ---- step 0b: feats->fp16, each CTA its own 32-row slice ----
    {
        const float* fsrc = feats + (size_t)bid * QB * CIN;
        __half*      fdst = g_F   + (size_t)bid * QB * CIN;
        #pragma unroll
        for (int t = 0; t < 2; t++) {
            int idx = tid + t * NT;           // 0..511 uint4 groups
            uint4 v = __ldg((const uint4*)fsrc + idx);
            uint2 h = make_uint2(h2pk(__uint_as_float(v.x), __uint_as_float(v.y)),
                                 h2pk(__uint_as_float(v.z), __uint_as_float(v.w)));
            *(uint2*)(fdst + idx * 4) = h;
        }
    }
    __threadfence();
    __syncthreads();
    if (tid == 0) atomicAdd(&g_cnt, 1);

    // ---- metadata ----
    for (int i = tid; i < QB * KN; i += NT) s_nidx[i] = nidx[m0 * KN + i];
    if (tid < NP * 3)  s_kp[tid] = kp[tid];
    if (tid < QB * 3)  s_q[tid]  = query[m0 * 3 + tid];

    // ---- grid-wide wait: g_F / g_B complete (all 512 CTAs co-resident) ----
    if (tid == 0) { while (atomicAdd(&g_cnt, 0) < 512) { } }
    __syncthreads();
    __threadfence();

    const int wid  = tid >> 5;
    const int lane = tid & 31;

    // frag addressing constants (verified)
    const int aprow = (lane & 7) + ((lane >> 3) & 1) * 8;
    const u32 abh   = (u32)(((lane >> 4) & 1) * 16);
    const int mgrp  = lane >> 3;
    const int krow  = (mgrp & 1) * 8 + (lane & 7);
    const u32 cbyte0 = (u32)((mgrp >> 1) * 16);

    #pragma unroll
    for (int sbch = 0; sbch < 2; sbch++) {
        __syncthreads();   // previous sub-batch fully consumed

        // gather fp16 features -> swizzled smem tile (16 queries, 256 rows)
        #pragma unroll
        for (int i = 0; i < 8; i++) {
            int g   = tid + i * NT;           // 0..2047
            int row = g >> 3;                 // local (q,k) row 0..255
            int c16 = g & 7;
            int m   = s_nidx[sbch * 256 + row];
            uint4 v = __ldg((const uint4*)(g_F + (size_t)m * CIN) + c16);
            u32 off = (u32)(row * 128) + (((u32)(c16 * 16)) ^ ((u32)(row & 7) * 16));
            *(uint4*)(sm + OFF_F + off) = v;
        }

        // influences -> fp16 smem [q][p(16) x k(16)] : one pair per thread
        {
            int qq = tid >> 4;
            int kk = tid & 15;
            int m  = s_nidx[sbch * 256 + tid];
            int qg = sbch * SB + qq;
            float rx = support[m * 3 + 0] - s_q[qg * 3 + 0];
            float ry = support[m * 3 + 1] - s_q[qg * 3 + 1];
            float rz = support[m * 3 + 2] - s_q[qg * 3 + 2];
            __half* ib = s_infl + qq * 256 + kk;
            #pragma unroll
            for (int p = 0; p < NP; p++) {
                float dx = rx - s_kp[p * 3 + 0];
                float dy = ry - s_kp[p * 3 + 1];
                float dz = rz - s_kp[p * 3 + 2];
                float d  = sqrtf(fmaf(dx, dx, fmaf(dy, dy, dz * dz)));
                ib[p * 16] = __float2half_rn(fmaxf(1.0f - d, 0.0f));
            }
            ib[15 * 16] = __half(0.0f);
        }
        __syncthreads();

        // per-query mma aggregation: 2 queries per warp
        #pragma unroll
        for (int i = 0; i < 2; i++) {
            const int q = wid * 2 + i;        // local query 0..15

            u32 a[4];
            ldmx4(a, sb + OFF_INFL + (u32)(q * 512 + aprow * 32) + abh);

            // preload ALL b-frags (reads complete before in-place staging)
            const int frow = q * 16 + krow;
            const u32 fbase = sb + OFF_F + (u32)(frow * 128);
            const u32 swz   = (u32)((krow & 7) * 16);
            u32 b[16];
            #pragma unroll
            for (int cc = 0; cc < 4; cc++)
                ldmx4t(&b[cc * 4], fbase + (((u32)(cc * 32) + cbyte0) ^ swz));

            const int prow = lane >> 2;
            const int c4   = lane & 3;
            #pragma unroll
            for (int cc = 0; cc < 4; cc++) {
                float acc[2][4];
                #pragma unroll
                for (int h = 0; h < 2; h++)
                    #pragma unroll
                    for (int e = 0; e < 4; e++) acc[h][e] = 0.0f;
                mma_f16(acc[0], a, &b[cc * 4]);
                mma_f16(acc[1], a, &b[cc * 4 + 2]);

                // stage into f-tile rows of query q (swizzled)
                #pragma unroll
                for (int h = 0; h < 2; h++) {
                    u32 lo = h2pk(acc[h][0], acc[h][1]);
                    u32 hi = h2pk(acc[h][2], acc[h][3]);
                    u32 x = (u32)((2 * cc + h) * 16);
                    *(u32*)(sm + OFF_F + (q * 16 + prow) * 128 +
                            ((x ^ ((u32)(prow & 7) * 16)) + (u32)(c4 * 4))) = lo;
                    *(u32*)(sm + OFF_F + (q * 16 + prow + 8) * 128 +
                            ((x ^ ((u32)((prow + 8) & 7) * 16)) + (u32)(c4 * 4))) = hi;
                }
            }
            __syncwarp();

            // coalesced write-out: 15 p-rows x 128B -> g_A row (m0+sbch*16+q)
            #pragma unroll
            for (int rnd = 0; rnd < 4; rnd++) {
                int u = lane + rnd * 32;
                if (u < 120) {
                    int p = u >> 3, j = u & 7;
                    uint4 v = *(uint4*)(sm + OFF_F + (q * 16 + p) * 128 +
                                        (((u32)(j * 16)) ^ ((u32)(p & 7) * 16)));
                    *(uint4*)(g_A + (size_t)(m0 + sbch * SB + q) * KTOT
                              + p * CIN + j * 8) = v;
                }
            }
            __syncwarp();
        }
    }

    // ---- own A rows visible at L2 ----
    __threadfence();
    __syncthreads();

    // ---- phase B: GEMM out[32 x 128] = A_own[32 x 960] @ B^T ----
    const int wm = wid >> 2;        // 0..1 (M groups of 16)
    const int wn = wid & 3;         // 0..3 (N groups of 32)

    const int a_row  = wm * 16 + aprow;
    const u32 a_mask = (u32)((a_row & 7) * 16);
    const int b_row  = wn * 32 + (lane & 7) + ((lane >> 4) & 1) * 8;
    const int b_bh   = ((lane >> 3) & 1) * 16;
    const u32 b_mask = (u32)((b_row & 7) * 16);

    float acc[4][4];
    #pragma unroll
    for (int ni = 0; ni < 4; ni++)
        #pragma unroll
        for (int e = 0; e < 4; e++) acc[ni][e] = 0.0f;

    auto load_chunk = [&](int c) {
        u32 dstb = sb + (u32)(c & 1) * BUFB;
        #pragma unroll
        for (int j = 0; j < 5; j++) {
            int idx = tid + j * NT;               // 0..1279
            const __half* src;
            u32 dst;
            if (idx < 256) {                      // A tile: 32 rows
                int row = idx >> 3, c16 = idx & 7;
                src = g_A + (size_t)(m0 + row) * KTOT + c * 64 + c16 * 8;
                dst = dstb + (u32)(row * 128 + ((c16 * 16) ^ ((row & 7) * 16)));
            } else {                              // B tile: 128 rows
                int w = idx - 256;
                int row = w >> 3, c16 = w & 7;
                src = g_B + (size_t)row * KTOT + c * 64 + c16 * 8;
                dst = dstb + ATILE
                    + (u32)(row * 128 + ((c16 * 16) ^ ((row & 7) * 16)));
            }
            asm volatile("cp.async.cg.shared.global [%0], [%1], 16;"
                         :: "r"(dst), "l"(src) : "memory");
        }
        asm volatile("cp.async.commit_group;" ::: "memory");
    };

    load_chunk(0);

    for (int c = 0; c < NCHUNK; c++) {
        if (c + 1 < NCHUNK) {
            load_chunk(c + 1);
            asm volatile("cp.async.wait_group 1;" ::: "memory");
        } else {
            asm volatile("cp.async.wait_group 0;" ::: "memory");
        }
        __syncthreads();

        const u32 bufb  = sb + (u32)(c & 1) * BUFB;
        const u32 aBase = bufb + (u32)(a_row * 128);
        const u32 bBase = bufb + ATILE + (u32)(b_row * 128);

        #pragma unroll
        for (int ks = 0; ks < 4; ks++) {
            const u32 aOff = (u32)((ks * 32)) + abh;
            const u32 bOff = (u32)((ks * 32 + b_bh)) ^ b_mask;

            u32 b[8];
            #pragma unroll
            for (int nj = 0; nj < 2; nj++)
                ldmx4(&b[nj * 4], bBase + (u32)(nj * 16 * 128) + bOff);

            u32 a[4];
            ldmx4(a, aBase + (aOff ^ a_mask));
            #pragma unroll
            for (int ni = 0; ni < 4; ni++)
                mma_f16(acc[ni], a, &b[(ni >> 1) * 4 + (ni & 1) * 2]);
        }
        __syncthreads();
    }

    // ---- epilogue ----
    {
        int row = m0 + wm * 16 + (lane >> 2);
        #pragma unroll
        for (int ni = 0; ni < 4; ni++) {
            int col = wn * 32 + ni * 8 + (lane & 3) * 2;
            *(float2*)(out + (size_t)row * COUT + col) =
                make_float2(acc[ni][0], acc[ni][1]);
            *(float2*)(out + (size_t)(row + 8) * COUT + col) =
                make_float2(acc[ni][2], acc[ni][3]);
        }
    }
}

// ================= launch =================
extern "C" void kernel_launch(void* const* d_in, const int* in_sizes, int n_in,
                              void* d_out, int out_size) {
    const float* query   = (const float*)d_in[0];
    const float* support = (const float*)d_in[1];
    const int*   nidx    = (const int*)d_in[2];
    const float* feats   = (const float*)d_in[3];
    const float* W       = (const float*)d_in[4];
    const float* kp      = (const float*)d_in[5];
    float* out = (float*)d_out;

    cudaFuncSetAttribute(kpconv_fused,
                         cudaFuncAttributeMaxDynamicSharedMemorySize, SMEM_TOT);
    kpconv_fused<<<NTOT / QB, NT, SMEM_TOT>>>(
        query, support, nidx, feats, kp, W, out);
}